// round 7
// baseline (speedup 1.0000x reference)
#include <cuda_runtime.h>
#include <cuda_fp16.h>
#include <cstdint>

// ---------------- problem constants ----------------
#define T_STEPS 10
#define B_SZ    8192
#define D_IN    1024
#define H1      512
#define H2      256
#define H3      128
#define N_OUT   10
#define M_TOT   (T_STEPS * B_SZ)                          // 81920
#define HALF_N  ((uint32_t)(T_STEPS * B_SZ * D_IN / 2))   // 41,943,040

// All activations use b-major rows: m = b*10 + t.
__device__ __half g_S  [(size_t)M_TOT * D_IN];            // 167 MB spikes, layer-0
__device__ __half g_s1 [(size_t)M_TOT * H1];
__device__ __half g_s2 [(size_t)M_TOT * H2];
__device__ float  g_s3sum[(size_t)B_SZ * H3];
__device__ __half g_W1s[2][(size_t)H1 * D_IN];
__device__ __half g_W2s[2][(size_t)H2 * H1];
__device__ __half g_W3s[2][(size_t)H3 * H2];

// ---------------- PTX helpers ----------------
__device__ __forceinline__ uint32_t smem_u32(const void* p) {
    uint32_t a;
    asm("{ .reg .u64 t; cvta.to.shared.u64 t, %1; cvt.u32.u64 %0, t; }" : "=r"(a) : "l"(p));
    return a;
}
__device__ __forceinline__ void cp16(uint32_t dst, const void* src) {
    asm volatile("cp.async.cg.shared.global [%0], [%1], 16;" :: "r"(dst), "l"(src) : "memory");
}
__device__ __forceinline__ void cp_commit() { asm volatile("cp.async.commit_group;" ::: "memory"); }
template<int N> __device__ __forceinline__ void cp_wait() {
    asm volatile("cp.async.wait_group %0;" :: "n"(N) : "memory");
}
__device__ __forceinline__ void ldsm4(uint32_t* r, uint32_t addr) {
    asm volatile("ldmatrix.sync.aligned.m8n8.x4.shared.b16 {%0,%1,%2,%3}, [%4];"
                 : "=r"(r[0]), "=r"(r[1]), "=r"(r[2]), "=r"(r[3]) : "r"(addr));
}
__device__ __forceinline__ void mma16816(float* d, const uint32_t* a, const uint32_t* b) {
    asm volatile(
        "mma.sync.aligned.m16n8k16.row.col.f32.f16.f16.f32 "
        "{%0,%1,%2,%3}, {%4,%5,%6,%7}, {%8,%9}, {%0,%1,%2,%3};"
        : "+f"(d[0]), "+f"(d[1]), "+f"(d[2]), "+f"(d[3])
        : "r"(a[0]), "r"(a[1]), "r"(a[2]), "r"(a[3]), "r"(b[0]), "r"(b[1]));
}

// ---------------- Threefry-2x32-20, key = (0, 42) ----------------
__device__ __forceinline__ uint32_t rotl32(uint32_t v, int r) {
    return (v << r) | (v >> (32 - r));
}
__device__ __forceinline__ void threefry_0_42(uint32_t x0, uint32_t x1,
                                              uint32_t& y0, uint32_t& y1) {
    const uint32_t k0 = 0u, k1 = 42u;
    const uint32_t k2 = k0 ^ k1 ^ 0x1BD11BDAu;
    x0 += k0; x1 += k1;
#define TF_RND(r) { x0 += x1; x1 = rotl32(x1, r); x1 ^= x0; }
    TF_RND(13) TF_RND(15) TF_RND(26) TF_RND(6)
    x0 += k1; x1 += k2 + 1u;
    TF_RND(17) TF_RND(29) TF_RND(16) TF_RND(24)
    x0 += k2; x1 += k0 + 2u;
    TF_RND(13) TF_RND(15) TF_RND(26) TF_RND(6)
    x0 += k0; x1 += k1 + 3u;
    TF_RND(17) TF_RND(29) TF_RND(16) TF_RND(24)
    x0 += k1; x1 += k2 + 4u;
    TF_RND(13) TF_RND(15) TF_RND(26) TF_RND(6)
    x0 += k2; x1 += k0 + 5u;
#undef TF_RND
    y0 = x0; y1 = x1;
}
__device__ __forceinline__ float bits_to_unit(uint32_t bits) {
    return __uint_as_float((bits >> 9) | 0x3f800000u) - 1.0f;
}

// Spike train written b-major: row = b*10 + t. Counter pair (i, i+HALF) is
// (t, t+5) of the SAME (b, d), so one index computation feeds both stores.
__global__ void spikegen_kernel(const float* __restrict__ images, __half* __restrict__ S) {
    uint32_t i = blockIdx.x * 256u + threadIdx.x;
    if (i >= HALF_N) return;
    uint32_t y0, y1;
    threefry_0_42(i, i + HALF_N, y0, y1);
    uint32_t t = i >> 23;                    // B*D = 2^23
    uint32_t r = i & 0x7FFFFFu;
    uint32_t b = r >> 10;
    uint32_t d = r & 1023u;
    float img = images[r];
    size_t base = ((size_t)b * 10u << 10) + d;       // (b*10)*1024 + d
    S[base + ((size_t)t << 10)]        = __float2half((bits_to_unit(y0) < img) ? 1.0f : 0.0f);
    S[base + ((size_t)(t + 5) << 10)]  = __float2half((bits_to_unit(y1) < img) ? 1.0f : 0.0f);
}

// ---------------- weight 2-way fp16 split (scaled residual) ----------------
__global__ void split_w_kernel(const float* __restrict__ W, __half* __restrict__ a,
                               __half* __restrict__ b, int n) {
    int i = blockIdx.x * 256 + threadIdx.x;
    if (i >= n) return;
    float w = W[i];
    __half h = __float2half(w);
    float r = w - __half2float(h);
    a[i] = h;
    b[i] = __float2half(r * 2048.0f);
}

// ---------------- fused GEMM + LIF ----------------
// C[BM,N] tile = A @ (Wa + 2^-11*Wb)^T, BM=160 (16 batches x 10 timesteps),
// BN=128, BK=32, 3-stage cp.async, 512 threads (16 warps: 2 m x 8 n),
// warp tile m80 x n16. Epilogue: stage acc in smem, exact-order LIF scan over t,
// write spikes (MODE 0) or spike-sum (MODE 1) directly. No cur buffers.
#define BMT 160
#define BNT 128
#define A_SZ   (BMT * 80)                  // 12800 B (rows: 32 fp16 + 8 pad)
#define W_SZ   (BNT * 80)                  // 10240 B
#define STAGE_SZ (A_SZ + 2 * W_SZ)         // 33280 B
#define N_STG  3
#define GEMM_SMEM (N_STG * STAGE_SZ)       // 99840 B
#define EPI_STRIDE 132                     // floats per staged row

__device__ __forceinline__ void load_chunk(
    const __half* __restrict__ A, const __half* __restrict__ Wa,
    const __half* __restrict__ Wb, uint32_t sbase, int stage,
    int m0, int n0, int K, int c, int tid)
{
    uint32_t st = sbase + stage * STAGE_SZ;
    const int k0 = c * 32;
    const __half* Ab = A + (size_t)m0 * K + k0;
#pragma unroll
    for (int i = tid; i < (BMT * 4); i += 512) {      // 640 cp16
        int row = i >> 2, q = i & 3;
        cp16(st + (uint32_t)(row * 80 + q * 16), Ab + (size_t)row * K + q * 8);
    }
    const __half* const Ws[2] = {Wa, Wb};
#pragma unroll
    for (int s = 0; s < 2; s++) {
        const __half* Wp = Ws[s] + (size_t)n0 * K + k0;
        uint32_t bs = st + A_SZ + s * W_SZ;
        {
            int i = tid;                              // 512 cp16 exactly
            int row = i >> 2, q = i & 3;
            cp16(bs + (uint32_t)(row * 80 + q * 16), Wp + (size_t)row * K + q * 8);
        }
    }
    cp_commit();
}

template<int MODE>  // 0: LIF -> fp16 spikes; 1: LIF -> float spike sum
__global__ __launch_bounds__(512, 1)
void gemm_lif(const __half* __restrict__ A,
              const __half* __restrict__ Wa,
              const __half* __restrict__ Wb,
              const float* __restrict__ bias,
              __half* __restrict__ Sout,
              float* __restrict__ SumOut,
              int N, int K)
{
    extern __shared__ char smem[];
    const uint32_t sbase = smem_u32(smem);
    const int tid  = threadIdx.x;
    const int warp = tid >> 5;
    const int lane = tid & 31;
    const int wm = warp >> 3;                 // 0..1 -> m offset wm*80
    const int wn = warp & 7;                  // 0..7 -> n offset wn*16
    const int m0 = blockIdx.y * BMT;
    const int n0 = blockIdx.x * BNT;
    const int NC = K >> 5;

    float acc[5][2][4];
#pragma unroll
    for (int mt = 0; mt < 5; mt++)
#pragma unroll
        for (int nt = 0; nt < 2; nt++)
#pragma unroll
            for (int r = 0; r < 4; r++) acc[mt][nt][r] = 0.0f;

    load_chunk(A, Wa, Wb, sbase, 0, m0, n0, K, 0, tid);
    load_chunk(A, Wa, Wb, sbase, 1, m0, n0, K, 1, tid);

    const uint32_t a_row = (uint32_t)(lane & 15) * 80;
    const uint32_t a_col = (uint32_t)(lane >> 4) * 16;
    const uint32_t b_row = (uint32_t)((lane & 7) + ((lane >> 4) & 1) * 8) * 80;
    const uint32_t b_col = (uint32_t)((lane >> 3) & 1) * 16;
    const __half2 sc2 = __half2half2(__ushort_as_half((unsigned short)0x1000)); // 2^-11

    for (int c = 0; c < NC; c++) {
        if (c + 1 < NC) cp_wait<1>(); else cp_wait<0>();
        __syncthreads();                                   // single barrier per chunk
        if (c + 2 < NC)
            load_chunk(A, Wa, Wb, sbase, (c + 2) % N_STG, m0, n0, K, c + 2, tid);

        uint32_t st = sbase + (c % N_STG) * STAGE_SZ;
#pragma unroll
        for (int ks = 0; ks < 2; ks++) {
            uint32_t a[5][4];
#pragma unroll
            for (int mt = 0; mt < 5; mt++) {
                uint32_t addr = st + (uint32_t)(wm * 80 + mt * 16) * 80 + a_row
                              + (uint32_t)ks * 32 + a_col;
                ldsm4(a[mt], addr);
            }
            // term 0: A @ Wa
            {
                uint32_t r[4];
                ldsm4(r, st + A_SZ + (uint32_t)(wn * 16) * 80 + b_row
                         + (uint32_t)ks * 32 + b_col);
                uint32_t b0[2] = {r[0], r[1]}, b1[2] = {r[2], r[3]};
#pragma unroll
                for (int mt = 0; mt < 5; mt++) {
                    mma16816(acc[mt][0], a[mt], b0);
                    mma16816(acc[mt][1], a[mt], b1);
                }
            }
            // scale A fragment: spikes 1 -> 2^-11 (exact)
#pragma unroll
            for (int mt = 0; mt < 5; mt++)
#pragma unroll
                for (int j = 0; j < 4; j++) {
                    __half2 v = *(__half2*)&a[mt][j];
                    v = __hmul2(v, sc2);
                    a[mt][j] = *(uint32_t*)&v;
                }
            // term 1: (2^-11 A) @ Wb
            {
                uint32_t r[4];
                ldsm4(r, st + A_SZ + W_SZ + (uint32_t)(wn * 16) * 80 + b_row
                         + (uint32_t)ks * 32 + b_col);
                uint32_t b0[2] = {r[0], r[1]}, b1[2] = {r[2], r[3]};
#pragma unroll
                for (int mt = 0; mt < 5; mt++) {
                    mma16816(acc[mt][0], a[mt], b0);
                    mma16816(acc[mt][1], a[mt], b1);
                }
            }
        }
    }

    // ---- epilogue: stage acc in smem (reuse pipeline buffers), LIF scan over t ----
    __syncthreads();
    float* ep = (float*)smem;                 // BMT x EPI_STRIDE floats = 84480 B
#pragma unroll
    for (int nt = 0; nt < 2; nt++) {
        const int col = wn * 16 + nt * 8 + (lane & 3) * 2;
#pragma unroll
        for (int mt = 0; mt < 5; mt++) {
            const int r0 = wm * 80 + mt * 16 + (lane >> 2);
            *(float2*)&ep[(size_t)r0 * EPI_STRIDE + col] =
                make_float2(acc[mt][nt][0], acc[mt][nt][1]);
            *(float2*)&ep[(size_t)(r0 + 8) * EPI_STRIDE + col] =
                make_float2(acc[mt][nt][2], acc[mt][nt][3]);
        }
    }
    __syncthreads();

    // 16 batches x 128 cols = 2048 (b,col) pairs; 4 per thread
    const int bg = blockIdx.y * 16;           // first batch of this tile
#pragma unroll
    for (int it = 0; it < 4; it++) {
        int pair = it * 512 + tid;
        int lb = pair >> 7;                   // 0..15
        int col = pair & 127;
        float bz = bias[n0 + col];
        float mem = 0.0f;
        float s = 0.0f;
        const size_t gb = (size_t)(bg + lb);
#pragma unroll
        for (int t = 0; t < T_STEPS; t++) {
            float cur = __fadd_rn(ep[(size_t)(lb * 10 + t) * EPI_STRIDE + col], bz);
            float rst = (mem > 1.0f) ? 1.0f : 0.0f;
            mem = __fmul_rn(0.9f, mem);
            mem = __fadd_rn(mem, cur);
            mem = __fsub_rn(mem, rst);
            bool spk = (__fsub_rn(mem, 1.0f) > 0.0f);
            if (MODE == 0) {
                Sout[(gb * 10 + t) * (size_t)N + (n0 + col)] =
                    __float2half(spk ? 1.0f : 0.0f);
            } else {
                if (spk) s += 1.0f;
            }
        }
        if (MODE == 1) SumOut[gb * 128 + col] = s;
    }
}

// ---------------- head: Z = S3sum @ W4^T + 10*b4, softmax ----------------
__global__ void head_kernel(const float* __restrict__ S3sum, const float* __restrict__ W4,
                            const float* __restrict__ b4, float* __restrict__ out) {
    int b = blockIdx.x * 256 + threadIdx.x;
    if (b >= B_SZ) return;
    float acc[N_OUT];
#pragma unroll
    for (int c = 0; c < N_OUT; c++) acc[c] = 10.0f * b4[c];
    const float* row = S3sum + (size_t)b * H3;
#pragma unroll 4
    for (int j = 0; j < H3; j++) {
        float x = row[j];
#pragma unroll
        for (int c = 0; c < N_OUT; c++) acc[c] += x * __ldg(&W4[c * H3 + j]);
    }
    float m = acc[0];
#pragma unroll
    for (int c = 1; c < N_OUT; c++) m = fmaxf(m, acc[c]);
    float sum = 0.0f, e[N_OUT];
#pragma unroll
    for (int c = 0; c < N_OUT; c++) { e[c] = expf(acc[c] - m); sum += e[c]; }
    float inv = 1.0f / sum;
#pragma unroll
    for (int c = 0; c < N_OUT; c++) out[(size_t)b * N_OUT + c] = e[c] * inv;
}

// ---------------- launch ----------------
extern "C" void kernel_launch(void* const* d_in, const int* in_sizes, int n_in,
                              void* d_out, int out_size) {
    const float* images = (const float*)d_in[0];
    const float* W1 = (const float*)d_in[1];
    const float* b1 = (const float*)d_in[2];
    const float* W2 = (const float*)d_in[3];
    const float* b2 = (const float*)d_in[4];
    const float* W3 = (const float*)d_in[5];
    const float* b3 = (const float*)d_in[6];
    const float* W4 = (const float*)d_in[7];
    const float* b4 = (const float*)d_in[8];
    float* out = (float*)d_out;

    __half *S, *s1, *s2, *W1s, *W2s, *W3s;
    float *s3sum;
    cudaGetSymbolAddress((void**)&S,     g_S);
    cudaGetSymbolAddress((void**)&s1,    g_s1);
    cudaGetSymbolAddress((void**)&s2,    g_s2);
    cudaGetSymbolAddress((void**)&s3sum, g_s3sum);
    cudaGetSymbolAddress((void**)&W1s,   g_W1s);
    cudaGetSymbolAddress((void**)&W2s,   g_W2s);
    cudaGetSymbolAddress((void**)&W3s,   g_W3s);

    cudaFuncSetAttribute(gemm_lif<0>, cudaFuncAttributeMaxDynamicSharedMemorySize, GEMM_SMEM);
    cudaFuncSetAttribute(gemm_lif<1>, cudaFuncAttributeMaxDynamicSharedMemorySize, GEMM_SMEM);

    const size_t n1 = (size_t)H1 * D_IN, n2 = (size_t)H2 * H1, n3 = (size_t)H3 * H2;
    split_w_kernel<<<(int)((n1 + 255) / 256), 256>>>(W1, W1s, W1s + n1, (int)n1);
    split_w_kernel<<<(int)((n2 + 255) / 256), 256>>>(W2, W2s, W2s + n2, (int)n2);
    split_w_kernel<<<(int)((n3 + 255) / 256), 256>>>(W3, W3s, W3s + n3, (int)n3);

    spikegen_kernel<<<(HALF_N + 255) / 256, 256>>>(images, S);

    gemm_lif<0><<<dim3(H1 / BNT, M_TOT / BMT), 512, GEMM_SMEM>>>(
        S, W1s, W1s + n1, b1, s1, nullptr, H1, D_IN);

    gemm_lif<0><<<dim3(H2 / BNT, M_TOT / BMT), 512, GEMM_SMEM>>>(
        s1, W2s, W2s + n2, b2, s2, nullptr, H2, H1);

    gemm_lif<1><<<dim3(H3 / BNT, M_TOT / BMT), 512, GEMM_SMEM>>>(
        s2, W3s, W3s + n3, b3, nullptr, s3sum, H3, H2);

    head_kernel<<<(B_SZ + 255) / 256, 256>>>(s3sum, W4, b4, out);
}

// round 9
// speedup vs baseline: 1.2115x; 1.2115x over previous
#include <cuda_runtime.h>
#include <cuda_fp16.h>
#include <cstdint>

// ---------------- problem constants ----------------
#define T_STEPS 10
#define B_SZ    8192
#define D_IN    1024
#define H1      512
#define H2      256
#define H3      128
#define N_OUT   10
#define M_TOT   (T_STEPS * B_SZ)                          // 81920
#define HALF_N  ((uint32_t)(T_STEPS * B_SZ * D_IN / 2))   // 41,943,040

// t-major rows: m = t*B + b (R6 layout)
__device__ __half g_S   [(size_t)M_TOT * D_IN];           // 167 MB fp16 spikes
__device__ float  g_cur1[(size_t)M_TOT * H1];
__device__ __half g_s1  [(size_t)M_TOT * H1];
__device__ float  g_cur2[(size_t)M_TOT * H2];
__device__ __half g_s2  [(size_t)M_TOT * H2];
__device__ float  g_cur3[(size_t)M_TOT * H3];
__device__ float  g_s3sum[(size_t)B_SZ * H3];
__device__ __half g_W1s[2][(size_t)H1 * D_IN];
__device__ __half g_W2s[2][(size_t)H2 * H1];
__device__ __half g_W3s[2][(size_t)H3 * H2];

// ---------------- PTX helpers ----------------
__device__ __forceinline__ uint32_t smem_u32(const void* p) {
    uint32_t a;
    asm("{ .reg .u64 t; cvta.to.shared.u64 t, %1; cvt.u32.u64 %0, t; }" : "=r"(a) : "l"(p));
    return a;
}
__device__ __forceinline__ void cp16(uint32_t dst, const void* src) {
    asm volatile("cp.async.cg.shared.global [%0], [%1], 16;" :: "r"(dst), "l"(src) : "memory");
}
__device__ __forceinline__ void cp_commit() { asm volatile("cp.async.commit_group;" ::: "memory"); }
template<int N> __device__ __forceinline__ void cp_wait() {
    asm volatile("cp.async.wait_group %0;" :: "n"(N) : "memory");
}
__device__ __forceinline__ void ldsm4(uint32_t* r, uint32_t addr) {
    asm volatile("ldmatrix.sync.aligned.m8n8.x4.shared.b16 {%0,%1,%2,%3}, [%4];"
                 : "=r"(r[0]), "=r"(r[1]), "=r"(r[2]), "=r"(r[3]) : "r"(addr));
}
__device__ __forceinline__ void mma16816(float* d, const uint32_t* a, const uint32_t* b) {
    asm volatile(
        "mma.sync.aligned.m16n8k16.row.col.f32.f16.f16.f32 "
        "{%0,%1,%2,%3}, {%4,%5,%6,%7}, {%8,%9}, {%0,%1,%2,%3};"
        : "+f"(d[0]), "+f"(d[1]), "+f"(d[2]), "+f"(d[3])
        : "r"(a[0]), "r"(a[1]), "r"(a[2]), "r"(a[3]), "r"(b[0]), "r"(b[1]));
}

// ---------------- Threefry-2x32-20, key = (0, 42) ----------------
__device__ __forceinline__ uint32_t rotl32(uint32_t v, int r) {
    return (v << r) | (v >> (32 - r));
}
__device__ __forceinline__ void threefry_0_42(uint32_t x0, uint32_t x1,
                                              uint32_t& y0, uint32_t& y1) {
    const uint32_t k0 = 0u, k1 = 42u;
    const uint32_t k2 = k0 ^ k1 ^ 0x1BD11BDAu;
    x0 += k0; x1 += k1;
#define TF_RND(r) { x0 += x1; x1 = rotl32(x1, r); x1 ^= x0; }
    TF_RND(13) TF_RND(15) TF_RND(26) TF_RND(6)
    x0 += k1; x1 += k2 + 1u;
    TF_RND(17) TF_RND(29) TF_RND(16) TF_RND(24)
    x0 += k2; x1 += k0 + 2u;
    TF_RND(13) TF_RND(15) TF_RND(26) TF_RND(6)
    x0 += k0; x1 += k1 + 3u;
    TF_RND(17) TF_RND(29) TF_RND(16) TF_RND(24)
    x0 += k1; x1 += k2 + 4u;
    TF_RND(13) TF_RND(15) TF_RND(26) TF_RND(6)
    x0 += k2; x1 += k0 + 5u;
#undef TF_RND
    y0 = x0; y1 = x1;
}
__device__ __forceinline__ float bits_to_unit(uint32_t bits) {
    return __uint_as_float((bits >> 9) | 0x3f800000u) - 1.0f;
}

__global__ void spikegen_kernel(const float* __restrict__ images, __half* __restrict__ S) {
    uint32_t i = blockIdx.x * 256u + threadIdx.x;
    if (i >= HALF_N) return;
    uint32_t y0, y1;
    threefry_0_42(i, i + HALF_N, y0, y1);
    float img = images[i & ((B_SZ * D_IN) - 1u)];
    S[i]          = __float2half((bits_to_unit(y0) < img) ? 1.0f : 0.0f);
    S[i + HALF_N] = __float2half((bits_to_unit(y1) < img) ? 1.0f : 0.0f);
}

// ---------------- weight 2-way fp16 split (scaled residual) ----------------
// w ≈ wa + 2^-11 * wb; error ≤ 2^-23*|w|.
__global__ void split_w_kernel(const float* __restrict__ W, __half* __restrict__ a,
                               __half* __restrict__ b, int n) {
    int i = blockIdx.x * 256 + threadIdx.x;
    if (i >= n) return;
    float w = W[i];
    __half h = __float2half(w);
    float r = w - __half2float(h);
    a[i] = h;
    b[i] = __float2half(r * 2048.0f);
}

// ---------------- mma.sync GEMM: C = A @ (Wa + 2^-11*Wb)^T + bias ----------------
// BM=128, BN=128, BK=64, 2 stages, ONE barrier per chunk, 256 threads
// (8 warps, 2x4), warp tile m64 x n32. Rows padded to 72 fp16 = 144 B
// (4-bank shift/row -> conflict-free ldmatrix).
#define ROWB 144
#define A_SZ   (128 * ROWB)                 // 18432 B
#define W_SZ   (128 * ROWB)                 // 18432 B
#define STAGE_SZ (A_SZ + 2 * W_SZ)          // 55296 B
#define GEMM_SMEM (2 * STAGE_SZ)            // 110592 B

__device__ __forceinline__ void load_chunk(
    const __half* __restrict__ A, const __half* __restrict__ Wa,
    const __half* __restrict__ Wb, uint32_t sbase, int stage,
    int m0, int n0, int K, int c, int tid)
{
    uint32_t st = sbase + stage * STAGE_SZ;
    const int k0 = c * 64;
    const __half* Ab = A + (size_t)m0 * K + k0;
#pragma unroll
    for (int i = 0; i < 4; i++) {                 // 1024 cp16 for A
        int idx = i * 256 + tid;
        int row = idx >> 3, q = idx & 7;
        cp16(st + (uint32_t)(row * ROWB + q * 16), Ab + (size_t)row * K + q * 8);
    }
    const __half* const Ws[2] = {Wa, Wb};
#pragma unroll
    for (int s = 0; s < 2; s++) {
        const __half* Wp = Ws[s] + (size_t)n0 * K + k0;
        uint32_t bs = st + A_SZ + s * W_SZ;
#pragma unroll
        for (int i = 0; i < 4; i++) {
            int idx = i * 256 + tid;
            int row = idx >> 3, q = idx & 7;
            cp16(bs + (uint32_t)(row * ROWB + q * 16), Wp + (size_t)row * K + q * 8);
        }
    }
    cp_commit();
}

__global__ __launch_bounds__(256, 2)
void gemm_mma(const __half* __restrict__ A,
              const __half* __restrict__ Wa,
              const __half* __restrict__ Wb,
              const float* __restrict__ bias,
              float* __restrict__ C, int N, int K)
{
    extern __shared__ char smem[];
    const uint32_t sbase = smem_u32(smem);
    const int tid  = threadIdx.x;
    const int warp = tid >> 5;
    const int lane = tid & 31;
    const int wm = warp >> 2;                 // 0..1 -> m offset wm*64
    const int wn = warp & 3;                  // 0..3 -> n offset wn*32
    const int m0 = blockIdx.y * 128;
    const int n0 = blockIdx.x * 128;
    const int NC = K >> 6;

    float acc[4][4][4];
#pragma unroll
    for (int mt = 0; mt < 4; mt++)
#pragma unroll
        for (int nt = 0; nt < 4; nt++)
#pragma unroll
            for (int r = 0; r < 4; r++) acc[mt][nt][r] = 0.0f;

    load_chunk(A, Wa, Wb, sbase, 0, m0, n0, K, 0, tid);

    const uint32_t a_row = (uint32_t)(lane & 15) * ROWB;
    const uint32_t a_col = (uint32_t)(lane >> 4) * 16;
    const uint32_t b_row = (uint32_t)((lane & 7) + ((lane >> 4) & 1) * 8) * ROWB;
    const uint32_t b_col = (uint32_t)((lane >> 3) & 1) * 16;
    const __half2 sc2 = __half2half2(__ushort_as_half((unsigned short)0x1000)); // 2^-11

    for (int c = 0; c < NC; c++) {
        cp_wait<0>();            // chunk c resident
        __syncthreads();         // + all reads of the other stage (iter c-1) done
        if (c + 1 < NC)
            load_chunk(A, Wa, Wb, sbase, (c + 1) & 1, m0, n0, K, c + 1, tid);

        uint32_t st = sbase + (c & 1) * STAGE_SZ;
#pragma unroll
        for (int ks = 0; ks < 4; ks++) {
            uint32_t a[4][4];
#pragma unroll
            for (int mt = 0; mt < 4; mt++) {
                uint32_t addr = st + (uint32_t)(wm * 64 + mt * 16) * ROWB + a_row
                              + (uint32_t)ks * 32 + a_col;
                ldsm4(a[mt], addr);
            }
            // ---- term 0: A @ Wa ----
            {
                uint32_t bfr[4][2];
#pragma unroll
                for (int p = 0; p < 2; p++) {
                    uint32_t addr = st + A_SZ
                                  + (uint32_t)(wn * 32 + p * 16) * ROWB + b_row
                                  + (uint32_t)ks * 32 + b_col;
                    uint32_t r[4];
                    ldsm4(r, addr);
                    bfr[p * 2 + 0][0] = r[0]; bfr[p * 2 + 0][1] = r[1];
                    bfr[p * 2 + 1][0] = r[2]; bfr[p * 2 + 1][1] = r[3];
                }
#pragma unroll
                for (int mt = 0; mt < 4; mt++)
#pragma unroll
                    for (int nt = 0; nt < 4; nt++)
                        mma16816(acc[mt][nt], a[mt], bfr[nt]);
            }
            // scale A fragment: spikes 1 -> 2^-11 (exact)
#pragma unroll
            for (int mt = 0; mt < 4; mt++)
#pragma unroll
                for (int j = 0; j < 4; j++) {
                    __half2 v = *(__half2*)&a[mt][j];
                    v = __hmul2(v, sc2);
                    a[mt][j] = *(uint32_t*)&v;
                }
            // ---- term 1: (2^-11 * A) @ Wb ----
            {
                uint32_t bfr[4][2];
#pragma unroll
                for (int p = 0; p < 2; p++) {
                    uint32_t addr = st + A_SZ + W_SZ
                                  + (uint32_t)(wn * 32 + p * 16) * ROWB + b_row
                                  + (uint32_t)ks * 32 + b_col;
                    uint32_t r[4];
                    ldsm4(r, addr);
                    bfr[p * 2 + 0][0] = r[0]; bfr[p * 2 + 0][1] = r[1];
                    bfr[p * 2 + 1][0] = r[2]; bfr[p * 2 + 1][1] = r[3];
                }
#pragma unroll
                for (int mt = 0; mt < 4; mt++)
#pragma unroll
                    for (int nt = 0; nt < 4; nt++)
                        mma16816(acc[mt][nt], a[mt], bfr[nt]);
            }
        }
    }

    // epilogue: +bias, fp32 store
#pragma unroll
    for (int nt = 0; nt < 4; nt++) {
        const int ccol = n0 + wn * 32 + nt * 8 + (lane & 3) * 2;
        const float bz0 = __ldg(&bias[ccol]);
        const float bz1 = __ldg(&bias[ccol + 1]);
#pragma unroll
        for (int mt = 0; mt < 4; mt++) {
            const int r0 = m0 + wm * 64 + mt * 16 + (lane >> 2);
            float2 v0 = make_float2(acc[mt][nt][0] + bz0, acc[mt][nt][1] + bz1);
            float2 v1 = make_float2(acc[mt][nt][2] + bz0, acc[mt][nt][3] + bz1);
            *(float2*)(C + (size_t)r0 * N + ccol)       = v0;
            *(float2*)(C + (size_t)(r0 + 8) * N + ccol) = v1;
        }
    }
}

// ---------------- LIF scan (exact op order), fp16 spike out ----------------
__global__ void lif_kernel(const float* __restrict__ CUR, __half* __restrict__ S, int NBH) {
    int i = blockIdx.x * 256 + threadIdx.x;
    if (i >= NBH) return;
    float mem = 0.0f;
#pragma unroll
    for (int t = 0; t < T_STEPS; t++) {
        float cur = CUR[(size_t)t * NBH + i];
        float r = (mem > 1.0f) ? 1.0f : 0.0f;
        mem = __fmul_rn(0.9f, mem);
        mem = __fadd_rn(mem, cur);
        mem = __fsub_rn(mem, r);
        S[(size_t)t * NBH + i] =
            __float2half((__fsub_rn(mem, 1.0f) > 0.0f) ? 1.0f : 0.0f);
    }
}
__global__ void lif_sum_kernel(const float* __restrict__ CUR, float* __restrict__ Ssum, int NBH) {
    int i = blockIdx.x * 256 + threadIdx.x;
    if (i >= NBH) return;
    float mem = 0.0f, s = 0.0f;
#pragma unroll
    for (int t = 0; t < T_STEPS; t++) {
        float cur = CUR[(size_t)t * NBH + i];
        float r = (mem > 1.0f) ? 1.0f : 0.0f;
        mem = __fmul_rn(0.9f, mem);
        mem = __fadd_rn(mem, cur);
        mem = __fsub_rn(mem, r);
        if (__fsub_rn(mem, 1.0f) > 0.0f) s += 1.0f;
    }
    Ssum[i] = s;
}

// ---------------- head: Z = S3sum @ W4^T + 10*b4, softmax ----------------
__global__ void head_kernel(const float* __restrict__ S3sum, const float* __restrict__ W4,
                            const float* __restrict__ b4, float* __restrict__ out) {
    int b = blockIdx.x * 256 + threadIdx.x;
    if (b >= B_SZ) return;
    float acc[N_OUT];
#pragma unroll
    for (int c = 0; c < N_OUT; c++) acc[c] = 10.0f * b4[c];
    const float* row = S3sum + (size_t)b * H3;
#pragma unroll 4
    for (int j = 0; j < H3; j++) {
        float x = row[j];
        if (x != 0.0f) {
#pragma unroll
            for (int c = 0; c < N_OUT; c++) acc[c] += x * __ldg(&W4[c * H3 + j]);
        }
    }
    float m = acc[0];
#pragma unroll
    for (int c = 1; c < N_OUT; c++) m = fmaxf(m, acc[c]);
    float sum = 0.0f, e[N_OUT];
#pragma unroll
    for (int c = 0; c < N_OUT; c++) { e[c] = expf(acc[c] - m); sum += e[c]; }
    float inv = 1.0f / sum;
#pragma unroll
    for (int c = 0; c < N_OUT; c++) out[(size_t)b * N_OUT + c] = e[c] * inv;
}

// ---------------- launch ----------------
extern "C" void kernel_launch(void* const* d_in, const int* in_sizes, int n_in,
                              void* d_out, int out_size) {
    const float* images = (const float*)d_in[0];
    const float* W1 = (const float*)d_in[1];
    const float* b1 = (const float*)d_in[2];
    const float* W2 = (const float*)d_in[3];
    const float* b2 = (const float*)d_in[4];
    const float* W3 = (const float*)d_in[5];
    const float* b3 = (const float*)d_in[6];
    const float* W4 = (const float*)d_in[7];
    const float* b4 = (const float*)d_in[8];
    float* out = (float*)d_out;

    __half *S, *s1, *s2, *W1s, *W2s, *W3s;
    float *cur1, *cur2, *cur3, *s3sum;
    cudaGetSymbolAddress((void**)&S,     g_S);
    cudaGetSymbolAddress((void**)&cur1,  g_cur1);
    cudaGetSymbolAddress((void**)&s1,    g_s1);
    cudaGetSymbolAddress((void**)&cur2,  g_cur2);
    cudaGetSymbolAddress((void**)&s2,    g_s2);
    cudaGetSymbolAddress((void**)&cur3,  g_cur3);
    cudaGetSymbolAddress((void**)&s3sum, g_s3sum);
    cudaGetSymbolAddress((void**)&W1s,   g_W1s);
    cudaGetSymbolAddress((void**)&W2s,   g_W2s);
    cudaGetSymbolAddress((void**)&W3s,   g_W3s);

    cudaFuncSetAttribute(gemm_mma, cudaFuncAttributeMaxDynamicSharedMemorySize, GEMM_SMEM);

    const size_t n1 = (size_t)H1 * D_IN, n2 = (size_t)H2 * H1, n3 = (size_t)H3 * H2;
    split_w_kernel<<<(int)((n1 + 255) / 256), 256>>>(W1, W1s, W1s + n1, (int)n1);
    split_w_kernel<<<(int)((n2 + 255) / 256), 256>>>(W2, W2s, W2s + n2, (int)n2);
    split_w_kernel<<<(int)((n3 + 255) / 256), 256>>>(W3, W3s, W3s + n3, (int)n3);

    spikegen_kernel<<<(HALF_N + 255) / 256, 256>>>(images, S);

    gemm_mma<<<dim3(H1 / 128, M_TOT / 128), 256, GEMM_SMEM>>>(
        S, W1s, W1s + n1, b1, cur1, H1, D_IN);
    lif_kernel<<<(B_SZ * H1 + 255) / 256, 256>>>(cur1, s1, B_SZ * H1);

    gemm_mma<<<dim3(H2 / 128, M_TOT / 128), 256, GEMM_SMEM>>>(
        s1, W2s, W2s + n2, b2, cur2, H2, H1);
    lif_kernel<<<(B_SZ * H2 + 255) / 256, 256>>>(cur2, s2, B_SZ * H2);

    gemm_mma<<<dim3(H3 / 128, M_TOT / 128), 256, GEMM_SMEM>>>(
        s2, W3s, W3s + n3, b3, cur3, H3, H2);
    lif_sum_kernel<<<(B_SZ * H3 + 255) / 256, 256>>>(cur3, s3sum, B_SZ * H3);

    head_kernel<<<(B_SZ + 255) / 256, 256>>>(s3sum, W4, b4, out);
}